// round 1
// baseline (speedup 1.0000x reference)
#include <cuda_runtime.h>
#include <cstdint>

#define BATCH 8
#define SEQ   2048
#define EMB   256
#define QD    512
#define VD    512
#define MTOT  (BATCH*SEQ)   // 16384

#define BM 128
#define BN 128
#define BK 16
#define ASTR (BK+4)    // 20 floats: conflict-free A fragment LDS
#define BSTR (BN+8)    // 136 floats: conflict-free B fragment LDS
#define NTHR 256

// Scratch (device globals: allocation-free per harness rules)
__device__ float g_q[(size_t)MTOT*QD];           // 33.5 MB
__device__ float g_k[(size_t)MTOT*QD];           // 33.5 MB
__device__ float g_v[(size_t)MTOT*VD];           // 33.5 MB
__device__ float g_s[(size_t)BATCH*SEQ*SEQ];     // 134 MB (logits -> probs in place)

__device__ __forceinline__ void split_tf32(float a, uint32_t& hi, uint32_t& lo){
  asm("cvt.rna.tf32.f32 %0, %1;" : "=r"(hi) : "f"(a));
  float r = a - __uint_as_float(hi);     // exact (Sterbenz)
  asm("cvt.rna.tf32.f32 %0, %1;" : "=r"(lo) : "f"(r));
}

__device__ __forceinline__ void mma8(float c[4], const uint32_t a[4], const uint32_t b[2]){
  asm volatile(
    "mma.sync.aligned.m16n8k8.row.col.f32.tf32.tf32.f32 "
    "{%0,%1,%2,%3}, {%4,%5,%6,%7}, {%8,%9}, {%0,%1,%2,%3};"
    : "+f"(c[0]), "+f"(c[1]), "+f"(c[2]), "+f"(c[3])
    : "r"(a[0]), "r"(a[1]), "r"(a[2]), "r"(a[3]), "r"(b[0]), "r"(b[1]));
}

// Generic 128x128x16 double-buffered GEMM core.
// A is row-major [M,K] (K contiguous). B is either:
//   B_KCONTIG=true : row-major [N,K] (K contiguous) -> C = A @ B^T   (QK case)
//   B_KCONTIG=false: row-major [K,N] (N contiguous) -> C = A @ B     (proj/PV case)
// Accumulates with 3xTF32 split (hi*hi + hi*lo + lo*hi) for ~fp32 accuracy.
template<bool B_KCONTIG>
__device__ __forceinline__ void gemm_core(
    const float* __restrict__ A, int lda,
    const float* __restrict__ B, int ldb,
    int K, int m0, int n0, float acc[4][4][4])
{
  __shared__ float As[2][BM*ASTR];
  __shared__ float Bs[2][BK*BSTR];

  const int tid  = threadIdx.x;
  const int lane = tid & 31, warp = tid >> 5;
  const int wm = warp & 1, wn = warp >> 1;       // 2x4 warp grid, 64x32 warp tile
  const int mB = wm*64, nB = wn*32;
  const int ar = lane >> 2, ac = lane & 3;       // A fragment lane coords
  const int br = lane & 3,  bc = lane >> 2;      // B fragment lane coords

  const float* Ab = A + (size_t)m0*lda;
  const int aR = tid >> 2, aC = (tid & 3)*4;     // A tile: 128 rows x 16 cols, 2 float4/thread
  int bR, bC;
  if (B_KCONTIG){ bR = tid >> 2; bC = (tid & 3)*4; }   // 128 rows(n) x 16 cols(k)
  else          { bR = tid >> 5; bC = (tid & 31)*4; }  // 16 rows(k) x 128 cols(n)

  float4 va0, va1, vb0, vb1;

  auto ldg = [&](int kt){
    va0 = *(const float4*)(Ab + (size_t)aR*lda      + kt*BK + aC);
    va1 = *(const float4*)(Ab + (size_t)(aR+64)*lda + kt*BK + aC);
    if (B_KCONTIG){
      const float* Bb = B + (size_t)n0*ldb + kt*BK;
      vb0 = *(const float4*)(Bb + (size_t)bR*ldb      + bC);
      vb1 = *(const float4*)(Bb + (size_t)(bR+64)*ldb + bC);
    } else {
      const float* Bb = B + (size_t)(kt*BK)*ldb + n0;
      vb0 = *(const float4*)(Bb + (size_t)bR*ldb     + bC);
      vb1 = *(const float4*)(Bb + (size_t)(bR+8)*ldb + bC);
    }
  };

  auto sts = [&](int buf){
    float* a0 = &As[buf][aR*ASTR + aC];
    a0[0]=va0.x; a0[1]=va0.y; a0[2]=va0.z; a0[3]=va0.w;
    float* a1 = &As[buf][(aR+64)*ASTR + aC];
    a1[0]=va1.x; a1[1]=va1.y; a1[2]=va1.z; a1[3]=va1.w;
    if (B_KCONTIG){
      // transpose n-major global rows into k-major smem rows
      float* bp = &Bs[buf][0];
      bp[(bC+0)*BSTR + bR]    = vb0.x;
      bp[(bC+1)*BSTR + bR]    = vb0.y;
      bp[(bC+2)*BSTR + bR]    = vb0.z;
      bp[(bC+3)*BSTR + bR]    = vb0.w;
      bp[(bC+0)*BSTR + bR+64] = vb1.x;
      bp[(bC+1)*BSTR + bR+64] = vb1.y;
      bp[(bC+2)*BSTR + bR+64] = vb1.z;
      bp[(bC+3)*BSTR + bR+64] = vb1.w;
    } else {
      float* b0 = &Bs[buf][bR*BSTR + bC];
      b0[0]=vb0.x; b0[1]=vb0.y; b0[2]=vb0.z; b0[3]=vb0.w;
      float* b1 = &Bs[buf][(bR+8)*BSTR + bC];
      b1[0]=vb1.x; b1[1]=vb1.y; b1[2]=vb1.z; b1[3]=vb1.w;
    }
  };

  auto compute = [&](int buf){
    #pragma unroll
    for (int ks=0; ks<2; ks++){
      uint32_t ah[4][4], al[4][4];
      #pragma unroll
      for (int mi=0; mi<4; mi++){
        const float* p = &As[buf][(mB + mi*16 + ar)*ASTR + ks*8 + ac];
        split_tf32(p[0],        ah[mi][0], al[mi][0]);
        split_tf32(p[8*ASTR],   ah[mi][1], al[mi][1]);
        split_tf32(p[4],        ah[mi][2], al[mi][2]);
        split_tf32(p[8*ASTR+4], ah[mi][3], al[mi][3]);
      }
      uint32_t bh[4][2], bl[4][2];
      #pragma unroll
      for (int ni=0; ni<4; ni++){
        const float* p = &Bs[buf][(ks*8 + br)*BSTR + nB + ni*8 + bc];
        split_tf32(p[0],      bh[ni][0], bl[ni][0]);
        split_tf32(p[4*BSTR], bh[ni][1], bl[ni][1]);
      }
      #pragma unroll
      for (int mi=0; mi<4; mi++){
        #pragma unroll
        for (int ni=0; ni<4; ni++){
          mma8(acc[mi][ni], al[mi], bh[ni]);   // lo*hi
          mma8(acc[mi][ni], ah[mi], bl[ni]);   // hi*lo
          mma8(acc[mi][ni], ah[mi], bh[ni]);   // hi*hi
        }
      }
    }
  };

  const int KT = K / BK;
  ldg(0); sts(0);
  __syncthreads();
  for (int kt=0; kt<KT; kt++){
    int cur = kt & 1;
    if (kt+1 < KT) ldg(kt+1);
    compute(cur);
    if (kt+1 < KT){ sts(cur^1); __syncthreads(); }
  }
}

// ------------------------- kernels -------------------------

__global__ __launch_bounds__(NTHR) void proj_kernel(
    const float* __restrict__ x,
    const float* __restrict__ Wq, const float* __restrict__ bq,
    const float* __restrict__ Wk, const float* __restrict__ bk,
    const float* __restrict__ Wv, const float* __restrict__ bv)
{
  const int z = blockIdx.z;
  const float* W    = (z==0) ? Wq : (z==1) ? Wk : Wv;
  const float* bias = (z==0) ? bq : (z==1) ? bk : bv;
  float* C          = (z==0) ? g_q : (z==1) ? g_k : g_v;

  const int m0 = blockIdx.y*BM, n0 = blockIdx.x*BN;
  float acc[4][4][4];
  #pragma unroll
  for (int i=0;i<4;i++)
    #pragma unroll
    for (int j=0;j<4;j++)
      #pragma unroll
      for (int l=0;l<4;l++) acc[i][j][l]=0.f;

  gemm_core<false>(x, EMB, W, QD, EMB, m0, n0, acc);

  const int lane = threadIdx.x & 31, warp = threadIdx.x >> 5;
  const int rowB = m0 + (warp&1)*64 + (lane>>2);
  const int colB = n0 + (warp>>1)*32 + (lane&3)*2;
  #pragma unroll
  for (int mi=0; mi<4; mi++){
    #pragma unroll
    for (int ni=0; ni<4; ni++){
      int c0 = colB + ni*8;
      float b0 = bias[c0], b1 = bias[c0+1];
      #pragma unroll
      for (int h=0; h<2; h++){
        int r = rowB + mi*16 + h*8;
        float v0 = acc[mi][ni][h*2+0] + b0;
        float v1 = acc[mi][ni][h*2+1] + b1;
        if (z==0){ v0 = 1.f/(1.f+__expf(-v0)); v1 = 1.f/(1.f+__expf(-v1)); }
        C[(size_t)r*QD + c0]   = v0;
        C[(size_t)r*QD + c0+1] = v1;
      }
    }
  }
}

__global__ __launch_bounds__(NTHR) void qk_kernel()
{
  const int b = blockIdx.z;
  const float* Q  = g_q + (size_t)b*SEQ*QD;
  const float* Km = g_k + (size_t)b*SEQ*QD;
  float* S        = g_s + (size_t)b*SEQ*SEQ;

  const int m0 = blockIdx.y*BM, n0 = blockIdx.x*BN;
  float acc[4][4][4];
  #pragma unroll
  for (int i=0;i<4;i++)
    #pragma unroll
    for (int j=0;j<4;j++)
      #pragma unroll
      for (int l=0;l<4;l++) acc[i][j][l]=0.f;

  gemm_core<true>(Q, QD, Km, QD, QD, m0, n0, acc);

  const int lane = threadIdx.x & 31, warp = threadIdx.x >> 5;
  const int rowB = m0 + (warp&1)*64 + (lane>>2);
  const int colB = n0 + (warp>>1)*32 + (lane&3)*2;
  const float scale = 0.0625f;   // 1/sqrt(256)
  #pragma unroll
  for (int mi=0; mi<4; mi++){
    #pragma unroll
    for (int ni=0; ni<4; ni++){
      int c0 = colB + ni*8;
      #pragma unroll
      for (int h=0; h<2; h++){
        int r = rowB + mi*16 + h*8;
        float v0 = acc[mi][ni][h*2+0] * scale;
        float v1 = acc[mi][ni][h*2+1] * scale;
        v0 = (v0 > 0.f) ? v0 : (__expf(v0) - 1.f);   // ELU, alpha=1
        v1 = (v1 > 0.f) ? v1 : (__expf(v1) - 1.f);
        S[(size_t)r*SEQ + c0]   = v0;
        S[(size_t)r*SEQ + c0+1] = v1;
      }
    }
  }
}

__global__ __launch_bounds__(256) void softmax_kernel()
{
  const size_t row = blockIdx.x;
  float* S = g_s + row*SEQ;
  const int t = threadIdx.x;

  float4 u0 = *(const float4*)(S + t*8);
  float4 u1 = *(const float4*)(S + t*8 + 4);
  float v[8] = {u0.x,u0.y,u0.z,u0.w,u1.x,u1.y,u1.z,u1.w};

  float m = v[0];
  #pragma unroll
  for (int i=1;i<8;i++) m = fmaxf(m, v[i]);
  #pragma unroll
  for (int o=16;o;o>>=1) m = fmaxf(m, __shfl_xor_sync(0xffffffffu, m, o));

  __shared__ float red[8];
  __shared__ float bmax, bsum;
  if ((t&31)==0) red[t>>5] = m;
  __syncthreads();
  if (t==0){
    float mm = red[0];
    #pragma unroll
    for (int i=1;i<8;i++) mm = fmaxf(mm, red[i]);
    bmax = mm;
  }
  __syncthreads();
  m = bmax;

  float s = 0.f;
  #pragma unroll
  for (int i=0;i<8;i++){ v[i] = __expf(v[i]-m); s += v[i]; }
  #pragma unroll
  for (int o=16;o;o>>=1) s += __shfl_xor_sync(0xffffffffu, s, o);
  if ((t&31)==0) red[t>>5] = s;
  __syncthreads();
  if (t==0){
    float ss = 0.f;
    #pragma unroll
    for (int i=0;i<8;i++) ss += red[i];
    bsum = ss;
  }
  __syncthreads();
  float inv = 1.f / bsum;

  *(float4*)(S + t*8)     = make_float4(v[0]*inv, v[1]*inv, v[2]*inv, v[3]*inv);
  *(float4*)(S + t*8 + 4) = make_float4(v[4]*inv, v[5]*inv, v[6]*inv, v[7]*inv);
}

__global__ __launch_bounds__(NTHR) void pv_kernel(float* __restrict__ out)
{
  const int b = blockIdx.z;
  const float* P = g_s + (size_t)b*SEQ*SEQ;
  const float* V = g_v + (size_t)b*SEQ*VD;
  float* O       = out + (size_t)b*SEQ*VD;

  const int m0 = blockIdx.y*BM, n0 = blockIdx.x*BN;
  float acc[4][4][4];
  #pragma unroll
  for (int i=0;i<4;i++)
    #pragma unroll
    for (int j=0;j<4;j++)
      #pragma unroll
      for (int l=0;l<4;l++) acc[i][j][l]=0.f;

  gemm_core<false>(P, SEQ, V, VD, SEQ, m0, n0, acc);

  const int lane = threadIdx.x & 31, warp = threadIdx.x >> 5;
  const int rowB = m0 + (warp&1)*64 + (lane>>2);
  const int colB = n0 + (warp>>1)*32 + (lane&3)*2;
  #pragma unroll
  for (int mi=0; mi<4; mi++){
    #pragma unroll
    for (int ni=0; ni<4; ni++){
      int c0 = colB + ni*8;
      #pragma unroll
      for (int h=0; h<2; h++){
        int r = rowB + mi*16 + h*8;
        O[(size_t)r*VD + c0]   = acc[mi][ni][h*2+0];
        O[(size_t)r*VD + c0+1] = acc[mi][ni][h*2+1];
      }
    }
  }
}

// ------------------------- launch -------------------------

extern "C" void kernel_launch(void* const* d_in, const int* in_sizes, int n_in,
                              void* d_out, int out_size)
{
  (void)in_sizes; (void)n_in; (void)out_size;
  const float* x  = (const float*)d_in[0];
  const float* Wq = (const float*)d_in[1];
  const float* bq = (const float*)d_in[2];
  const float* Wk = (const float*)d_in[3];
  const float* bk = (const float*)d_in[4];
  const float* Wv = (const float*)d_in[5];
  const float* bv = (const float*)d_in[6];
  float* out = (float*)d_out;

  dim3 gp(QD/BN, MTOT/BM, 3);        // 4 x 128 x 3
  proj_kernel<<<gp, NTHR>>>(x, Wq, bq, Wk, bk, Wv, bv);

  dim3 gqk(SEQ/BN, SEQ/BM, BATCH);   // 16 x 16 x 8
  qk_kernel<<<gqk, NTHR>>>();

  softmax_kernel<<<MTOT, 256>>>();   // 16384 rows

  dim3 gpv(VD/BN, SEQ/BM, BATCH);    // 4 x 16 x 8
  pv_kernel<<<gpv, NTHR>>>(out);
}

// round 2
// speedup vs baseline: 1.8258x; 1.8258x over previous
#include <cuda_runtime.h>
#include <cstdint>

#define BATCH 8
#define SEQ   2048
#define EMB   256
#define QD    512
#define VD    512
#define MTOT  (BATCH*SEQ)   // 16384

#define BM 128
#define BN 128
#define BK 16
#define ASTR (BK+4)    // 20 floats: conflict-free A fragment LDS
#define BSTR (BN+8)    // 136 floats: conflict-free B fragment LDS
#define NTHR 256

// Scratch (device globals: allocation-free per harness rules)
__device__ float g_q[(size_t)MTOT*QD];           // 33.5 MB
__device__ float g_k[(size_t)MTOT*QD];           // 33.5 MB
__device__ float g_v[(size_t)MTOT*VD];           // 33.5 MB
__device__ float g_s[(size_t)BATCH*SEQ*SEQ];     // 134 MB (logits -> probs in place)

__device__ __forceinline__ void split_tf32(float a, uint32_t& hi, uint32_t& lo){
  asm("cvt.rna.tf32.f32 %0, %1;" : "=r"(hi) : "f"(a));
  float r = a - __uint_as_float(hi);     // exact (Sterbenz)
  asm("cvt.rna.tf32.f32 %0, %1;" : "=r"(lo) : "f"(r));
}

__device__ __forceinline__ uint32_t to_tf32(float a){
  uint32_t r;
  asm("cvt.rna.tf32.f32 %0, %1;" : "=r"(r) : "f"(a));
  return r;
}

__device__ __forceinline__ void mma8(float c[4], const uint32_t a[4], const uint32_t b[2]){
  asm volatile(
    "mma.sync.aligned.m16n8k8.row.col.f32.tf32.tf32.f32 "
    "{%0,%1,%2,%3}, {%4,%5,%6,%7}, {%8,%9}, {%0,%1,%2,%3};"
    : "+f"(c[0]), "+f"(c[1]), "+f"(c[2]), "+f"(c[3])
    : "r"(a[0]), "r"(a[1]), "r"(a[2]), "r"(a[3]), "r"(b[0]), "r"(b[1]));
}

// Generic 128x128x16 double-buffered GEMM core.
// A is row-major [M,K] (K contiguous). B is either:
//   B_KCONTIG=true : row-major [N,K] (K contiguous) -> C = A @ B^T   (QK case)
//   B_KCONTIG=false: row-major [K,N] (N contiguous) -> C = A @ B     (proj/PV case)
// SPLIT3=true:  3xTF32 split (hi*hi + hi*lo + lo*hi), ~fp32 accuracy.
// SPLIT3=false: single-pass tf32 (~5e-4 input rounding), 3x less tensor work.
template<bool B_KCONTIG, bool SPLIT3>
__device__ __forceinline__ void gemm_core(
    const float* __restrict__ A, int lda,
    const float* __restrict__ B, int ldb,
    int K, int m0, int n0, float acc[4][4][4])
{
  __shared__ float As[2][BM*ASTR];
  __shared__ float Bs[2][BK*BSTR];

  const int tid  = threadIdx.x;
  const int lane = tid & 31, warp = tid >> 5;
  const int wm = warp & 1, wn = warp >> 1;       // 2x4 warp grid, 64x32 warp tile
  const int mB = wm*64, nB = wn*32;
  const int ar = lane >> 2, ac = lane & 3;       // A fragment lane coords
  const int br = lane & 3,  bc = lane >> 2;      // B fragment lane coords

  const float* Ab = A + (size_t)m0*lda;
  const int aR = tid >> 2, aC = (tid & 3)*4;     // A tile: 128 rows x 16 cols, 2 float4/thread
  int bR, bC;
  if (B_KCONTIG){ bR = tid >> 2; bC = (tid & 3)*4; }   // 128 rows(n) x 16 cols(k)
  else          { bR = tid >> 5; bC = (tid & 31)*4; }  // 16 rows(k) x 128 cols(n)

  float4 va0, va1, vb0, vb1;

  auto ldg = [&](int kt){
    va0 = *(const float4*)(Ab + (size_t)aR*lda      + kt*BK + aC);
    va1 = *(const float4*)(Ab + (size_t)(aR+64)*lda + kt*BK + aC);
    if (B_KCONTIG){
      const float* Bb = B + (size_t)n0*ldb + kt*BK;
      vb0 = *(const float4*)(Bb + (size_t)bR*ldb      + bC);
      vb1 = *(const float4*)(Bb + (size_t)(bR+64)*ldb + bC);
    } else {
      const float* Bb = B + (size_t)(kt*BK)*ldb + n0;
      vb0 = *(const float4*)(Bb + (size_t)bR*ldb     + bC);
      vb1 = *(const float4*)(Bb + (size_t)(bR+8)*ldb + bC);
    }
  };

  auto sts = [&](int buf){
    float* a0 = &As[buf][aR*ASTR + aC];
    a0[0]=va0.x; a0[1]=va0.y; a0[2]=va0.z; a0[3]=va0.w;
    float* a1 = &As[buf][(aR+64)*ASTR + aC];
    a1[0]=va1.x; a1[1]=va1.y; a1[2]=va1.z; a1[3]=va1.w;
    if (B_KCONTIG){
      // transpose n-major global rows into k-major smem rows
      float* bp = &Bs[buf][0];
      bp[(bC+0)*BSTR + bR]    = vb0.x;
      bp[(bC+1)*BSTR + bR]    = vb0.y;
      bp[(bC+2)*BSTR + bR]    = vb0.z;
      bp[(bC+3)*BSTR + bR]    = vb0.w;
      bp[(bC+0)*BSTR + bR+64] = vb1.x;
      bp[(bC+1)*BSTR + bR+64] = vb1.y;
      bp[(bC+2)*BSTR + bR+64] = vb1.z;
      bp[(bC+3)*BSTR + bR+64] = vb1.w;
    } else {
      float* b0 = &Bs[buf][bR*BSTR + bC];
      b0[0]=vb0.x; b0[1]=vb0.y; b0[2]=vb0.z; b0[3]=vb0.w;
      float* b1 = &Bs[buf][(bR+8)*BSTR + bC];
      b1[0]=vb1.x; b1[1]=vb1.y; b1[2]=vb1.z; b1[3]=vb1.w;
    }
  };

  auto compute = [&](int buf){
    #pragma unroll
    for (int ks=0; ks<2; ks++){
      uint32_t ah[4][4], al[4][4];
      #pragma unroll
      for (int mi=0; mi<4; mi++){
        const float* p = &As[buf][(mB + mi*16 + ar)*ASTR + ks*8 + ac];
        if (SPLIT3){
          split_tf32(p[0],        ah[mi][0], al[mi][0]);
          split_tf32(p[8*ASTR],   ah[mi][1], al[mi][1]);
          split_tf32(p[4],        ah[mi][2], al[mi][2]);
          split_tf32(p[8*ASTR+4], ah[mi][3], al[mi][3]);
        } else {
          ah[mi][0] = to_tf32(p[0]);
          ah[mi][1] = to_tf32(p[8*ASTR]);
          ah[mi][2] = to_tf32(p[4]);
          ah[mi][3] = to_tf32(p[8*ASTR+4]);
        }
      }
      uint32_t bh[4][2], bl[4][2];
      #pragma unroll
      for (int ni=0; ni<4; ni++){
        const float* p = &Bs[buf][(ks*8 + br)*BSTR + nB + ni*8 + bc];
        if (SPLIT3){
          split_tf32(p[0],      bh[ni][0], bl[ni][0]);
          split_tf32(p[4*BSTR], bh[ni][1], bl[ni][1]);
        } else {
          bh[ni][0] = to_tf32(p[0]);
          bh[ni][1] = to_tf32(p[4*BSTR]);
        }
      }
      #pragma unroll
      for (int mi=0; mi<4; mi++){
        #pragma unroll
        for (int ni=0; ni<4; ni++){
          if (SPLIT3){
            mma8(acc[mi][ni], al[mi], bh[ni]);   // lo*hi
            mma8(acc[mi][ni], ah[mi], bl[ni]);   // hi*lo
          }
          mma8(acc[mi][ni], ah[mi], bh[ni]);     // hi*hi
        }
      }
    }
  };

  const int KT = K / BK;
  ldg(0); sts(0);
  __syncthreads();
  for (int kt=0; kt<KT; kt++){
    int cur = kt & 1;
    if (kt+1 < KT) ldg(kt+1);
    compute(cur);
    if (kt+1 < KT){ sts(cur^1); __syncthreads(); }
  }
}

// ------------------------- kernels -------------------------

__global__ __launch_bounds__(NTHR) void proj_kernel(
    const float* __restrict__ x,
    const float* __restrict__ Wq, const float* __restrict__ bq,
    const float* __restrict__ Wk, const float* __restrict__ bk,
    const float* __restrict__ Wv, const float* __restrict__ bv)
{
  const int z = blockIdx.z;
  const float* W    = (z==0) ? Wq : (z==1) ? Wk : Wv;
  const float* bias = (z==0) ? bq : (z==1) ? bk : bv;
  float* C          = (z==0) ? g_q : (z==1) ? g_k : g_v;

  const int m0 = blockIdx.y*BM, n0 = blockIdx.x*BN;
  float acc[4][4][4];
  #pragma unroll
  for (int i=0;i<4;i++)
    #pragma unroll
    for (int j=0;j<4;j++)
      #pragma unroll
      for (int l=0;l<4;l++) acc[i][j][l]=0.f;

  gemm_core<false, true>(x, EMB, W, QD, EMB, m0, n0, acc);

  const int lane = threadIdx.x & 31, warp = threadIdx.x >> 5;
  const int rowB = m0 + (warp&1)*64 + (lane>>2);
  const int colB = n0 + (warp>>1)*32 + (lane&3)*2;
  #pragma unroll
  for (int mi=0; mi<4; mi++){
    #pragma unroll
    for (int ni=0; ni<4; ni++){
      int c0 = colB + ni*8;
      float b0 = bias[c0], b1 = bias[c0+1];
      #pragma unroll
      for (int h=0; h<2; h++){
        int r = rowB + mi*16 + h*8;
        float v0 = acc[mi][ni][h*2+0] + b0;
        float v1 = acc[mi][ni][h*2+1] + b1;
        if (z==0){ v0 = 1.f/(1.f+__expf(-v0)); v1 = 1.f/(1.f+__expf(-v1)); }
        C[(size_t)r*QD + c0]   = v0;
        C[(size_t)r*QD + c0+1] = v1;
      }
    }
  }
}

__global__ __launch_bounds__(NTHR, 2) void qk_kernel()
{
  const int b = blockIdx.z;
  const float* Q  = g_q + (size_t)b*SEQ*QD;
  const float* Km = g_k + (size_t)b*SEQ*QD;
  float* S        = g_s + (size_t)b*SEQ*SEQ;

  const int m0 = blockIdx.y*BM, n0 = blockIdx.x*BN;
  float acc[4][4][4];
  #pragma unroll
  for (int i=0;i<4;i++)
    #pragma unroll
    for (int j=0;j<4;j++)
      #pragma unroll
      for (int l=0;l<4;l++) acc[i][j][l]=0.f;

  gemm_core<true, false>(Q, QD, Km, QD, QD, m0, n0, acc);

  const int lane = threadIdx.x & 31, warp = threadIdx.x >> 5;
  const int rowB = m0 + (warp&1)*64 + (lane>>2);
  const int colB = n0 + (warp>>1)*32 + (lane&3)*2;
  const float scale = 0.0625f;   // 1/sqrt(256)
  #pragma unroll
  for (int mi=0; mi<4; mi++){
    #pragma unroll
    for (int ni=0; ni<4; ni++){
      int c0 = colB + ni*8;
      #pragma unroll
      for (int h=0; h<2; h++){
        int r = rowB + mi*16 + h*8;
        float v0 = acc[mi][ni][h*2+0] * scale;
        float v1 = acc[mi][ni][h*2+1] * scale;
        v0 = (v0 > 0.f) ? v0 : (__expf(v0) - 1.f);   // ELU, alpha=1
        v1 = (v1 > 0.f) ? v1 : (__expf(v1) - 1.f);
        S[(size_t)r*SEQ + c0]   = v0;
        S[(size_t)r*SEQ + c0+1] = v1;
      }
    }
  }
}

__global__ __launch_bounds__(256) void softmax_kernel()
{
  const size_t row = blockIdx.x;
  float* S = g_s + row*SEQ;
  const int t = threadIdx.x;

  float4 u0 = *(const float4*)(S + t*8);
  float4 u1 = *(const float4*)(S + t*8 + 4);
  float v[8] = {u0.x,u0.y,u0.z,u0.w,u1.x,u1.y,u1.z,u1.w};

  float m = v[0];
  #pragma unroll
  for (int i=1;i<8;i++) m = fmaxf(m, v[i]);
  #pragma unroll
  for (int o=16;o;o>>=1) m = fmaxf(m, __shfl_xor_sync(0xffffffffu, m, o));

  __shared__ float red[8];
  __shared__ float bmax, bsum;
  if ((t&31)==0) red[t>>5] = m;
  __syncthreads();
  if (t==0){
    float mm = red[0];
    #pragma unroll
    for (int i=1;i<8;i++) mm = fmaxf(mm, red[i]);
    bmax = mm;
  }
  __syncthreads();
  m = bmax;

  float s = 0.f;
  #pragma unroll
  for (int i=0;i<8;i++){ v[i] = __expf(v[i]-m); s += v[i]; }
  #pragma unroll
  for (int o=16;o;o>>=1) s += __shfl_xor_sync(0xffffffffu, s, o);
  if ((t&31)==0) red[t>>5] = s;
  __syncthreads();
  if (t==0){
    float ss = 0.f;
    #pragma unroll
    for (int i=0;i<8;i++) ss += red[i];
    bsum = ss;
  }
  __syncthreads();
  float inv = 1.f / bsum;

  *(float4*)(S + t*8)     = make_float4(v[0]*inv, v[1]*inv, v[2]*inv, v[3]*inv);
  *(float4*)(S + t*8 + 4) = make_float4(v[4]*inv, v[5]*inv, v[6]*inv, v[7]*inv);
}

__global__ __launch_bounds__(NTHR, 2) void pv_kernel(float* __restrict__ out)
{
  const int b = blockIdx.z;
  const float* P = g_s + (size_t)b*SEQ*SEQ;
  const float* V = g_v + (size_t)b*SEQ*VD;
  float* O       = out + (size_t)b*SEQ*VD;

  const int m0 = blockIdx.y*BM, n0 = blockIdx.x*BN;
  float acc[4][4][4];
  #pragma unroll
  for (int i=0;i<4;i++)
    #pragma unroll
    for (int j=0;j<4;j++)
      #pragma unroll
      for (int l=0;l<4;l++) acc[i][j][l]=0.f;

  gemm_core<false, false>(P, SEQ, V, VD, SEQ, m0, n0, acc);

  const int lane = threadIdx.x & 31, warp = threadIdx.x >> 5;
  const int rowB = m0 + (warp&1)*64 + (lane>>2);
  const int colB = n0 + (warp>>1)*32 + (lane&3)*2;
  #pragma unroll
  for (int mi=0; mi<4; mi++){
    #pragma unroll
    for (int ni=0; ni<4; ni++){
      int c0 = colB + ni*8;
      #pragma unroll
      for (int h=0; h<2; h++){
        int r = rowB + mi*16 + h*8;
        O[(size_t)r*VD + c0]   = acc[mi][ni][h*2+0];
        O[(size_t)r*VD + c0+1] = acc[mi][ni][h*2+1];
      }
    }
  }
}

// ------------------------- launch -------------------------

extern "C" void kernel_launch(void* const* d_in, const int* in_sizes, int n_in,
                              void* d_out, int out_size)
{
  (void)in_sizes; (void)n_in; (void)out_size;
  const float* x  = (const float*)d_in[0];
  const float* Wq = (const float*)d_in[1];
  const float* bq = (const float*)d_in[2];
  const float* Wk = (const float*)d_in[3];
  const float* bk = (const float*)d_in[4];
  const float* Wv = (const float*)d_in[5];
  const float* bv = (const float*)d_in[6];
  float* out = (float*)d_out;

  dim3 gp(QD/BN, MTOT/BM, 3);        // 4 x 128 x 3
  proj_kernel<<<gp, NTHR>>>(x, Wq, bq, Wk, bk, Wv, bv);

  dim3 gqk(SEQ/BN, SEQ/BM, BATCH);   // 16 x 16 x 8
  qk_kernel<<<gqk, NTHR>>>();

  softmax_kernel<<<MTOT, 256>>>();   // 16384 rows

  dim3 gpv(VD/BN, SEQ/BM, BATCH);    // 4 x 16 x 8
  pv_kernel<<<gpv, NTHR>>>(out);
}

// round 4
// speedup vs baseline: 2.1093x; 1.1553x over previous
#include <cuda_runtime.h>
#include <cstdint>

#define BATCH 8
#define SEQ   2048
#define EMB   256
#define QD    512
#define VD    512
#define MTOT  (BATCH*SEQ)   // 16384

#define BM 128
#define BN 128
#define BK 16
#define ASTR (BK+4)    // 20: conflict-free A fragment LDS
#define BSTR (BN+8)    // 136: conflict-free B fragment LDS
#define NTHR 256

// Scratch (device globals: allocation-free per harness rules)
__device__ float g_q[(size_t)MTOT*QD];           // 33.5 MB
__device__ float g_k[(size_t)MTOT*QD];           // 33.5 MB
__device__ float g_v[(size_t)MTOT*VD];           // 33.5 MB
__device__ float g_s[(size_t)BATCH*SEQ*SEQ];     // 134 MB (logits -> probs in place)

__device__ __forceinline__ uint32_t to_tf32(float a){
  uint32_t r;
  asm("cvt.rna.tf32.f32 %0, %1;" : "=r"(r) : "f"(a));
  return r;
}

__device__ __forceinline__ void mma8(float c[4], const uint32_t a[4], const uint32_t b[2]){
  asm volatile(
    "mma.sync.aligned.m16n8k8.row.col.f32.tf32.tf32.f32 "
    "{%0,%1,%2,%3}, {%4,%5,%6,%7}, {%8,%9}, {%0,%1,%2,%3};"
    : "+f"(c[0]), "+f"(c[1]), "+f"(c[2]), "+f"(c[3])
    : "r"(a[0]), "r"(a[1]), "r"(a[2]), "r"(a[3]), "r"(b[0]), "r"(b[1]));
}

// 128x128x16 double-buffered tf32 GEMM core (single-pass tf32).
// Values are converted to tf32 ONCE at the STS stage; the inner loop is
// pure LDS + MMA (no cvt) to maximize tensor-pipe issue share.
// A is row-major [M,K] (K contiguous). B is either:
//   B_KCONTIG=true : row-major [N,K] (K contiguous) -> C = A @ B^T   (QK case)
//   B_KCONTIG=false: row-major [K,N] (N contiguous) -> C = A @ B     (proj/PV case)
template<bool B_KCONTIG>
__device__ __forceinline__ void gemm_core(
    const float* __restrict__ A, int lda,
    const float* __restrict__ B, int ldb,
    int K, int m0, int n0, float acc[4][4][4])
{
  __shared__ uint32_t As[2][BM*ASTR];
  __shared__ uint32_t Bs[2][BK*BSTR];

  const int tid  = threadIdx.x;
  const int lane = tid & 31, warp = tid >> 5;
  const int wm = warp & 1, wn = warp >> 1;       // 2x4 warp grid, 64x32 warp tile
  const int mB = wm*64, nB = wn*32;
  const int ar = lane >> 2, ac = lane & 3;       // A fragment lane coords
  const int br = lane & 3,  bc = lane >> 2;      // B fragment lane coords

  const float* Ab = A + (size_t)m0*lda;
  const int aR = tid >> 2, aC = (tid & 3)*4;     // A tile: 128 rows x 16 cols, 2 float4/thread
  int bR, bC;
  if (B_KCONTIG){ bR = tid >> 2; bC = (tid & 3)*4; }   // 128 rows(n) x 16 cols(k)
  else          { bR = tid >> 5; bC = (tid & 31)*4; }  // 16 rows(k) x 128 cols(n)

  float4 va0, va1, vb0, vb1;

  auto ldg = [&](int kt){
    va0 = *(const float4*)(Ab + (size_t)aR*lda      + kt*BK + aC);
    va1 = *(const float4*)(Ab + (size_t)(aR+64)*lda + kt*BK + aC);
    if (B_KCONTIG){
      const float* Bb = B + (size_t)n0*ldb + kt*BK;
      vb0 = *(const float4*)(Bb + (size_t)bR*ldb      + bC);
      vb1 = *(const float4*)(Bb + (size_t)(bR+64)*ldb + bC);
    } else {
      const float* Bb = B + (size_t)(kt*BK)*ldb + n0;
      vb0 = *(const float4*)(Bb + (size_t)bR*ldb     + bC);
      vb1 = *(const float4*)(Bb + (size_t)(bR+8)*ldb + bC);
    }
  };

  auto sts = [&](int buf){
    uint32_t* a0 = &As[buf][aR*ASTR + aC];
    a0[0]=to_tf32(va0.x); a0[1]=to_tf32(va0.y); a0[2]=to_tf32(va0.z); a0[3]=to_tf32(va0.w);
    uint32_t* a1 = &As[buf][(aR+64)*ASTR + aC];
    a1[0]=to_tf32(va1.x); a1[1]=to_tf32(va1.y); a1[2]=to_tf32(va1.z); a1[3]=to_tf32(va1.w);
    if (B_KCONTIG){
      // transpose n-major global rows into k-major smem rows
      uint32_t* bp = &Bs[buf][0];
      bp[(bC+0)*BSTR + bR]    = to_tf32(vb0.x);
      bp[(bC+1)*BSTR + bR]    = to_tf32(vb0.y);
      bp[(bC+2)*BSTR + bR]    = to_tf32(vb0.z);
      bp[(bC+3)*BSTR + bR]    = to_tf32(vb0.w);
      bp[(bC+0)*BSTR + bR+64] = to_tf32(vb1.x);
      bp[(bC+1)*BSTR + bR+64] = to_tf32(vb1.y);
      bp[(bC+2)*BSTR + bR+64] = to_tf32(vb1.z);
      bp[(bC+3)*BSTR + bR+64] = to_tf32(vb1.w);
    } else {
      uint32_t* b0 = &Bs[buf][bR*BSTR + bC];
      b0[0]=to_tf32(vb0.x); b0[1]=to_tf32(vb0.y); b0[2]=to_tf32(vb0.z); b0[3]=to_tf32(vb0.w);
      uint32_t* b1 = &Bs[buf][(bR+8)*BSTR + bC];
      b1[0]=to_tf32(vb1.x); b1[1]=to_tf32(vb1.y); b1[2]=to_tf32(vb1.z); b1[3]=to_tf32(vb1.w);
    }
  };

  auto compute = [&](int buf){
    #pragma unroll
    for (int ks=0; ks<2; ks++){
      uint32_t ah[4][4];
      #pragma unroll
      for (int mi=0; mi<4; mi++){
        const uint32_t* p = &As[buf][(mB + mi*16 + ar)*ASTR + ks*8 + ac];
        ah[mi][0] = p[0];
        ah[mi][1] = p[8*ASTR];
        ah[mi][2] = p[4];
        ah[mi][3] = p[8*ASTR+4];
      }
      uint32_t bh[4][2];
      #pragma unroll
      for (int ni=0; ni<4; ni++){
        const uint32_t* p = &Bs[buf][(ks*8 + br)*BSTR + nB + ni*8 + bc];
        bh[ni][0] = p[0];
        bh[ni][1] = p[4*BSTR];
      }
      #pragma unroll
      for (int mi=0; mi<4; mi++){
        #pragma unroll
        for (int ni=0; ni<4; ni++){
          mma8(acc[mi][ni], ah[mi], bh[ni]);
        }
      }
    }
  };

  const int KT = K / BK;
  ldg(0); sts(0);
  __syncthreads();
  for (int kt=0; kt<KT; kt++){
    int cur = kt & 1;
    if (kt+1 < KT) ldg(kt+1);
    compute(cur);
    if (kt+1 < KT){ sts(cur^1); __syncthreads(); }
  }
}

// ------------------------- kernels -------------------------

__global__ __launch_bounds__(NTHR, 2) void proj_kernel(
    const float* __restrict__ x,
    const float* __restrict__ Wq, const float* __restrict__ bq,
    const float* __restrict__ Wk, const float* __restrict__ bk,
    const float* __restrict__ Wv, const float* __restrict__ bv)
{
  const int z = blockIdx.z;
  const float* W    = (z==0) ? Wq : (z==1) ? Wk : Wv;
  const float* bias = (z==0) ? bq : (z==1) ? bk : bv;
  float* C          = (z==0) ? g_q : (z==1) ? g_k : g_v;

  const int m0 = blockIdx.y*BM, n0 = blockIdx.x*BN;
  float acc[4][4][4];
  #pragma unroll
  for (int i=0;i<4;i++)
    #pragma unroll
    for (int j=0;j<4;j++)
      #pragma unroll
      for (int l=0;l<4;l++) acc[i][j][l]=0.f;

  gemm_core<false>(x, EMB, W, QD, EMB, m0, n0, acc);

  const int lane = threadIdx.x & 31, warp = threadIdx.x >> 5;
  const int rowB = m0 + (warp&1)*64 + (lane>>2);
  const int colB = n0 + (warp>>1)*32 + (lane&3)*2;
  #pragma unroll
  for (int mi=0; mi<4; mi++){
    #pragma unroll
    for (int ni=0; ni<4; ni++){
      int c0 = colB + ni*8;
      float b0 = bias[c0], b1 = bias[c0+1];
      #pragma unroll
      for (int h=0; h<2; h++){
        int r = rowB + mi*16 + h*8;
        float v0 = acc[mi][ni][h*2+0] + b0;
        float v1 = acc[mi][ni][h*2+1] + b1;
        if (z==0){ v0 = 1.f/(1.f+__expf(-v0)); v1 = 1.f/(1.f+__expf(-v1)); }
        C[(size_t)r*QD + c0]   = v0;
        C[(size_t)r*QD + c0+1] = v1;
      }
    }
  }
}

__global__ __launch_bounds__(NTHR, 2) void qk_kernel()
{
  const int b = blockIdx.z;
  const float* Q  = g_q + (size_t)b*SEQ*QD;
  const float* Km = g_k + (size_t)b*SEQ*QD;
  float* S        = g_s + (size_t)b*SEQ*SEQ;

  const int m0 = blockIdx.y*BM, n0 = blockIdx.x*BN;
  float acc[4][4][4];
  #pragma unroll
  for (int i=0;i<4;i++)
    #pragma unroll
    for (int j=0;j<4;j++)
      #pragma unroll
      for (int l=0;l<4;l++) acc[i][j][l]=0.f;

  gemm_core<true>(Q, QD, Km, QD, QD, m0, n0, acc);

  const int lane = threadIdx.x & 31, warp = threadIdx.x >> 5;
  const int rowB = m0 + (warp&1)*64 + (lane>>2);
  const int colB = n0 + (warp>>1)*32 + (lane&3)*2;
  const float scale = 0.0625f;   // 1/sqrt(256)
  #pragma unroll
  for (int mi=0; mi<4; mi++){
    #pragma unroll
    for (int ni=0; ni<4; ni++){
      int c0 = colB + ni*8;
      #pragma unroll
      for (int h=0; h<2; h++){
        int r = rowB + mi*16 + h*8;
        float v0 = acc[mi][ni][h*2+0] * scale;
        float v1 = acc[mi][ni][h*2+1] * scale;
        v0 = (v0 > 0.f) ? v0 : (__expf(v0) - 1.f);   // ELU, alpha=1
        v1 = (v1 > 0.f) ? v1 : (__expf(v1) - 1.f);
        S[(size_t)r*SEQ + c0]   = v0;
        S[(size_t)r*SEQ + c0+1] = v1;
      }
    }
  }
}

__global__ __launch_bounds__(256) void softmax_kernel()
{
  const size_t row = blockIdx.x;
  float* S = g_s + row*SEQ;
  const int t = threadIdx.x;

  float4 u0 = *(const float4*)(S + t*8);
  float4 u1 = *(const float4*)(S + t*8 + 4);
  float v[8] = {u0.x,u0.y,u0.z,u0.w,u1.x,u1.y,u1.z,u1.w};

  float m = v[0];
  #pragma unroll
  for (int i=1;i<8;i++) m = fmaxf(m, v[i]);
  #pragma unroll
  for (int o=16;o;o>>=1) m = fmaxf(m, __shfl_xor_sync(0xffffffffu, m, o));

  __shared__ float red[8];
  __shared__ float bmax, bsum;
  if ((t&31)==0) red[t>>5] = m;
  __syncthreads();
  if (t==0){
    float mm = red[0];
    #pragma unroll
    for (int i=1;i<8;i++) mm = fmaxf(mm, red[i]);
    bmax = mm;
  }
  __syncthreads();
  m = bmax;

  float s = 0.f;
  #pragma unroll
  for (int i=0;i<8;i++){ v[i] = __expf(v[i]-m); s += v[i]; }
  #pragma unroll
  for (int o=16;o;o>>=1) s += __shfl_xor_sync(0xffffffffu, s, o);
  if ((t&31)==0) red[t>>5] = s;
  __syncthreads();
  if (t==0){
    float ss = 0.f;
    #pragma unroll
    for (int i=0;i<8;i++) ss += red[i];
    bsum = ss;
  }
  __syncthreads();
  float inv = 1.f / bsum;

  *(float4*)(S + t*8)     = make_float4(v[0]*inv, v[1]*inv, v[2]*inv, v[3]*inv);
  *(float4*)(S + t*8 + 4) = make_float4(v[4]*inv, v[5]*inv, v[6]*inv, v[7]*inv);
}

__global__ __launch_bounds__(NTHR, 2) void pv_kernel(float* __restrict__ out)
{
  const int b = blockIdx.z;
  const float* P = g_s + (size_t)b*SEQ*SEQ;
  const float* V = g_v + (size_t)b*SEQ*VD;
  float* O       = out + (size_t)b*SEQ*VD;

  const int m0 = blockIdx.y*BM, n0 = blockIdx.x*BN;
  float acc[4][4][4];
  #pragma unroll
  for (int i=0;i<4;i++)
    #pragma unroll
    for (int j=0;j<4;j++)
      #pragma unroll
      for (int l=0;l<4;l++) acc[i][j][l]=0.f;

  gemm_core<false>(P, SEQ, V, VD, SEQ, m0, n0, acc);

  const int lane = threadIdx.x & 31, warp = threadIdx.x >> 5;
  const int rowB = m0 + (warp&1)*64 + (lane>>2);
  const int colB = n0 + (warp>>1)*32 + (lane&3)*2;
  #pragma unroll
  for (int mi=0; mi<4; mi++){
    #pragma unroll
    for (int ni=0; ni<4; ni++){
      int c0 = colB + ni*8;
      #pragma unroll
      for (int h=0; h<2; h++){
        int r = rowB + mi*16 + h*8;
        O[(size_t)r*VD + c0]   = acc[mi][ni][h*2+0];
        O[(size_t)r*VD + c0+1] = acc[mi][ni][h*2+1];
      }
    }
  }
}

// ------------------------- launch -------------------------

extern "C" void kernel_launch(void* const* d_in, const int* in_sizes, int n_in,
                              void* d_out, int out_size)
{
  (void)in_sizes; (void)n_in; (void)out_size;
  const float* x  = (const float*)d_in[0];
  const float* Wq = (const float*)d_in[1];
  const float* bq = (const float*)d_in[2];
  const float* Wk = (const float*)d_in[3];
  const float* bk = (const float*)d_in[4];
  const float* Wv = (const float*)d_in[5];
  const float* bv = (const float*)d_in[6];
  float* out = (float*)d_out;

  dim3 gp(QD/BN, MTOT/BM, 3);        // 4 x 128 x 3
  proj_kernel<<<gp, NTHR>>>(x, Wq, bq, Wk, bk, Wv, bv);

  dim3 gqk(SEQ/BN, SEQ/BM, BATCH);   // 16 x 16 x 8
  qk_kernel<<<gqk, NTHR>>>();

  softmax_kernel<<<MTOT, 256>>>();   // 16384 rows

  dim3 gpv(VD/BN, SEQ/BM, BATCH);    // 4 x 16 x 8
  pv_kernel<<<gpv, NTHR>>>(out);
}

// round 5
// speedup vs baseline: 2.2530x; 1.0681x over previous
#include <cuda_runtime.h>
#include <cstdint>

#define BATCH 8
#define SEQ   2048
#define EMB   256
#define QD    512
#define VD    512
#define MTOT  (BATCH*SEQ)   // 16384

#define BM 128
#define BN 128
#define BK 16
#define ASTR 20        // floats; 80B row stride (16B-aligned, LDS conflict-free)
#define BSTR 136       // floats; 544B row stride (16B-aligned, conflict-free)
#define NTHR 256
#define STAGES 4

#define A_BYTES  (BM*ASTR*4)    // 10240 per stage
#define BK_BYTES (BM*ASTR*4)    // 10240 per stage (KMAJ: 128 n-rows x 16 k)
#define BN_BYTES (BK*BSTR*4)    // 8704  per stage (NMAJ: 16 k-rows x 128 n)

// Scratch (device globals: allocation-free per harness rules)
__device__ float g_q[(size_t)MTOT*QD];           // tf32-rounded values
__device__ float g_k[(size_t)MTOT*QD];
__device__ float g_v[(size_t)MTOT*VD];
__device__ float g_s[(size_t)BATCH*SEQ*SEQ];     // logits -> tf32-rounded probs

__device__ __forceinline__ uint32_t to_tf32(float a){
  uint32_t r;
  asm("cvt.rna.tf32.f32 %0, %1;" : "=r"(r) : "f"(a));
  return r;
}
__device__ __forceinline__ float round_tf32(float a){
  return __uint_as_float(to_tf32(a));
}

__device__ __forceinline__ void mma8(float c[4], const uint32_t a[4], const uint32_t b[2]){
  asm volatile(
    "mma.sync.aligned.m16n8k8.row.col.f32.tf32.tf32.f32 "
    "{%0,%1,%2,%3}, {%4,%5,%6,%7}, {%8,%9}, {%0,%1,%2,%3};"
    : "+f"(c[0]), "+f"(c[1]), "+f"(c[2]), "+f"(c[3])
    : "r"(a[0]), "r"(a[1]), "r"(a[2]), "r"(a[3]), "r"(b[0]), "r"(b[1]));
}

__device__ __forceinline__ void cp16(uint32_t dst, const void* src){
  asm volatile("cp.async.ca.shared.global [%0], [%1], 16;" :: "r"(dst), "l"(src) : "memory");
}
__device__ __forceinline__ void cp_commit(){
  asm volatile("cp.async.commit_group;" ::: "memory");
}
template<int N> __device__ __forceinline__ void cp_wait(){
  asm volatile("cp.async.wait_group %0;" :: "n"(N) : "memory");
}

// ---------------- cp.async 4-stage GEMM core (operands pre-rounded to tf32) ----
// C[128,128] = A[128,K] @ op(B).  A row-major K-contiguous (lda elems).
//  B_KMAJ=true : B rows are N (K-contiguous, ldb elems)  -> C = A @ B^T  (QK)
//  B_KMAJ=false: B rows are K (N-contiguous, ldb elems)  -> C = A @ B    (PV)
// A/B point at the tile base (caller applies m0/n0 offsets).
template<bool B_KMAJ>
__device__ __forceinline__ void gemm_cp_core(
    const float* __restrict__ A, int lda,
    const float* __restrict__ B, int ldb,
    int KT, char* smem, float acc[4][4][4])
{
  const int tid  = threadIdx.x;
  const int lane = tid & 31, warp = tid >> 5;
  const int mB = (warp & 1)*64, nB = (warp >> 1)*32;
  const int ar = lane >> 2, ac = lane & 3;
  const int br = lane & 3,  bc = lane >> 2;

  const uint32_t sA = (uint32_t)__cvta_generic_to_shared(smem);
  const int BB = B_KMAJ ? BK_BYTES : BN_BYTES;
  const uint32_t sB = sA + STAGES*A_BYTES;

  auto issue = [&](int kt){
    int st = kt & (STAGES-1);
    uint32_t da = sA + st*A_BYTES;
    #pragma unroll
    for (int i = 0; i < 2; i++){
      int c = tid + i*256;
      int row = c >> 2, col = c & 3;
      cp16(da + row*80 + col*16, A + (size_t)row*lda + kt*BK + col*4);
    }
    uint32_t db = sB + st*BB;
    if (B_KMAJ){
      #pragma unroll
      for (int i = 0; i < 2; i++){
        int c = tid + i*256;
        int row = c >> 2, col = c & 3;
        cp16(db + row*80 + col*16, B + (size_t)row*ldb + kt*BK + col*4);
      }
    } else {
      #pragma unroll
      for (int i = 0; i < 2; i++){
        int c = tid + i*256;
        int row = c >> 5, col = c & 31;
        cp16(db + row*544 + col*16, B + (size_t)(kt*BK + row)*ldb + col*4);
      }
    }
  };

  auto compute = [&](int st){
    const uint32_t* As = (const uint32_t*)(smem + st*A_BYTES);
    const uint32_t* Bs = (const uint32_t*)(smem + STAGES*A_BYTES + st*BB);
    #pragma unroll
    for (int ks = 0; ks < 2; ks++){
      uint32_t ah[4][4];
      #pragma unroll
      for (int mi = 0; mi < 4; mi++){
        const uint32_t* p = &As[(mB + mi*16 + ar)*ASTR + ks*8 + ac];
        ah[mi][0] = p[0];
        ah[mi][1] = p[8*ASTR];
        ah[mi][2] = p[4];
        ah[mi][3] = p[8*ASTR+4];
      }
      uint32_t bh[4][2];
      #pragma unroll
      for (int ni = 0; ni < 4; ni++){
        if (B_KMAJ){
          const uint32_t* p = &Bs[(nB + ni*8 + bc)*ASTR + ks*8 + br];
          bh[ni][0] = p[0];
          bh[ni][1] = p[4];
        } else {
          const uint32_t* p = &Bs[(ks*8 + br)*BSTR + nB + ni*8 + bc];
          bh[ni][0] = p[0];
          bh[ni][1] = p[4*BSTR];
        }
      }
      #pragma unroll
      for (int mi = 0; mi < 4; mi++)
        #pragma unroll
        for (int ni = 0; ni < 4; ni++)
          mma8(acc[mi][ni], ah[mi], bh[ni]);
    }
  };

  #pragma unroll
  for (int s = 0; s < STAGES-1; s++){
    if (s < KT) issue(s);
    cp_commit();
  }
  for (int kt = 0; kt < KT; kt++){
    cp_wait<STAGES-2>();
    __syncthreads();
    if (kt + STAGES-1 < KT) issue(kt + STAGES-1);
    cp_commit();
    compute(kt & (STAGES-1));
  }
}

// ---------------- register-staged core for proj (cvt at STS) -------------------
template<bool B_KCONTIG>
__device__ __forceinline__ void gemm_reg_core(
    const float* __restrict__ A, int lda,
    const float* __restrict__ B, int ldb,
    int K, int m0, int n0, float acc[4][4][4])
{
  __shared__ uint32_t As[2][BM*ASTR];
  __shared__ uint32_t Bs[2][BK*BSTR];

  const int tid  = threadIdx.x;
  const int lane = tid & 31, warp = tid >> 5;
  const int mB = (warp & 1)*64, nB = (warp >> 1)*32;
  const int ar = lane >> 2, ac = lane & 3;
  const int br = lane & 3,  bc = lane >> 2;

  const float* Ab = A + (size_t)m0*lda;
  const int aR = tid >> 2, aC = (tid & 3)*4;
  const int bR = tid >> 5, bC = (tid & 31)*4;   // NMAJOR only (proj)

  float4 va0, va1, vb0, vb1;

  auto ldg = [&](int kt){
    va0 = *(const float4*)(Ab + (size_t)aR*lda      + kt*BK + aC);
    va1 = *(const float4*)(Ab + (size_t)(aR+64)*lda + kt*BK + aC);
    const float* Bb = B + (size_t)(kt*BK)*ldb + n0;
    vb0 = *(const float4*)(Bb + (size_t)bR*ldb     + bC);
    vb1 = *(const float4*)(Bb + (size_t)(bR+8)*ldb + bC);
  };
  auto sts = [&](int buf){
    uint32_t* a0 = &As[buf][aR*ASTR + aC];
    a0[0]=to_tf32(va0.x); a0[1]=to_tf32(va0.y); a0[2]=to_tf32(va0.z); a0[3]=to_tf32(va0.w);
    uint32_t* a1 = &As[buf][(aR+64)*ASTR + aC];
    a1[0]=to_tf32(va1.x); a1[1]=to_tf32(va1.y); a1[2]=to_tf32(va1.z); a1[3]=to_tf32(va1.w);
    uint32_t* b0 = &Bs[buf][bR*BSTR + bC];
    b0[0]=to_tf32(vb0.x); b0[1]=to_tf32(vb0.y); b0[2]=to_tf32(vb0.z); b0[3]=to_tf32(vb0.w);
    uint32_t* b1 = &Bs[buf][(bR+8)*BSTR + bC];
    b1[0]=to_tf32(vb1.x); b1[1]=to_tf32(vb1.y); b1[2]=to_tf32(vb1.z); b1[3]=to_tf32(vb1.w);
  };
  auto compute = [&](int buf){
    #pragma unroll
    for (int ks=0; ks<2; ks++){
      uint32_t ah[4][4];
      #pragma unroll
      for (int mi=0; mi<4; mi++){
        const uint32_t* p = &As[buf][(mB + mi*16 + ar)*ASTR + ks*8 + ac];
        ah[mi][0] = p[0]; ah[mi][1] = p[8*ASTR]; ah[mi][2] = p[4]; ah[mi][3] = p[8*ASTR+4];
      }
      uint32_t bh[4][2];
      #pragma unroll
      for (int ni=0; ni<4; ni++){
        const uint32_t* p = &Bs[buf][(ks*8 + br)*BSTR + nB + ni*8 + bc];
        bh[ni][0] = p[0]; bh[ni][1] = p[4*BSTR];
      }
      #pragma unroll
      for (int mi=0; mi<4; mi++)
        #pragma unroll
        for (int ni=0; ni<4; ni++)
          mma8(acc[mi][ni], ah[mi], bh[ni]);
    }
  };

  const int KT = K / BK;
  ldg(0); sts(0);
  __syncthreads();
  for (int kt=0; kt<KT; kt++){
    int cur = kt & 1;
    if (kt+1 < KT) ldg(kt+1);
    compute(cur);
    if (kt+1 < KT){ sts(cur^1); __syncthreads(); }
  }
  (void)B_KCONTIG;
}

// ------------------------- kernels -------------------------

__global__ __launch_bounds__(NTHR, 2) void proj_kernel(
    const float* __restrict__ x,
    const float* __restrict__ Wq, const float* __restrict__ bq,
    const float* __restrict__ Wk, const float* __restrict__ bk,
    const float* __restrict__ Wv, const float* __restrict__ bv)
{
  const int z = blockIdx.z;
  const float* W    = (z==0) ? Wq : (z==1) ? Wk : Wv;
  const float* bias = (z==0) ? bq : (z==1) ? bk : bv;
  float* C          = (z==0) ? g_q : (z==1) ? g_k : g_v;

  const int m0 = blockIdx.y*BM, n0 = blockIdx.x*BN;
  float acc[4][4][4];
  #pragma unroll
  for (int i=0;i<4;i++)
    #pragma unroll
    for (int j=0;j<4;j++)
      #pragma unroll
      for (int l=0;l<4;l++) acc[i][j][l]=0.f;

  gemm_reg_core<false>(x, EMB, W, QD, EMB, m0, n0, acc);

  const int lane = threadIdx.x & 31, warp = threadIdx.x >> 5;
  const int rowB = m0 + (warp&1)*64 + (lane>>2);
  const int colB = n0 + (warp>>1)*32 + (lane&3)*2;
  #pragma unroll
  for (int mi=0; mi<4; mi++){
    #pragma unroll
    for (int ni=0; ni<4; ni++){
      int c0 = colB + ni*8;
      float b0 = bias[c0], b1 = bias[c0+1];
      #pragma unroll
      for (int h=0; h<2; h++){
        int r = rowB + mi*16 + h*8;
        float v0 = acc[mi][ni][h*2+0] + b0;
        float v1 = acc[mi][ni][h*2+1] + b1;
        if (z==0){ v0 = 1.f/(1.f+__expf(-v0)); v1 = 1.f/(1.f+__expf(-v1)); }
        // pre-round to tf32 so downstream GEMMs need no cvt
        C[(size_t)r*QD + c0]   = round_tf32(v0);
        C[(size_t)r*QD + c0+1] = round_tf32(v1);
      }
    }
  }
}

__global__ __launch_bounds__(NTHR, 2) void qk_kernel()
{
  extern __shared__ char smem[];
  const int b = blockIdx.z;
  const int m0 = blockIdx.y*BM, n0 = blockIdx.x*BN;
  const float* A = g_q + (size_t)b*SEQ*QD + (size_t)m0*QD;
  const float* B = g_k + (size_t)b*SEQ*QD + (size_t)n0*QD;

  float acc[4][4][4];
  #pragma unroll
  for (int i=0;i<4;i++)
    #pragma unroll
    for (int j=0;j<4;j++)
      #pragma unroll
      for (int l=0;l<4;l++) acc[i][j][l]=0.f;

  gemm_cp_core<true>(A, QD, B, QD, QD/BK, smem, acc);

  float* S = g_s + (size_t)b*SEQ*SEQ;
  const int lane = threadIdx.x & 31, warp = threadIdx.x >> 5;
  const int rowB = m0 + (warp&1)*64 + (lane>>2);
  const int colB = n0 + (warp>>1)*32 + (lane&3)*2;
  const float scale = 0.0625f;   // 1/sqrt(256)
  #pragma unroll
  for (int mi=0; mi<4; mi++){
    #pragma unroll
    for (int ni=0; ni<4; ni++){
      int c0 = colB + ni*8;
      #pragma unroll
      for (int h=0; h<2; h++){
        int r = rowB + mi*16 + h*8;
        float v0 = acc[mi][ni][h*2+0] * scale;
        float v1 = acc[mi][ni][h*2+1] * scale;
        v0 = (v0 > 0.f) ? v0 : (__expf(v0) - 1.f);   // ELU, alpha=1
        v1 = (v1 > 0.f) ? v1 : (__expf(v1) - 1.f);
        S[(size_t)r*SEQ + c0]   = v0;
        S[(size_t)r*SEQ + c0+1] = v1;
      }
    }
  }
}

__global__ __launch_bounds__(256) void softmax_kernel()
{
  const size_t row = blockIdx.x;
  float* S = g_s + row*SEQ;
  const int t = threadIdx.x;

  float4 u0 = *(const float4*)(S + t*8);
  float4 u1 = *(const float4*)(S + t*8 + 4);
  float v[8] = {u0.x,u0.y,u0.z,u0.w,u1.x,u1.y,u1.z,u1.w};

  float m = v[0];
  #pragma unroll
  for (int i=1;i<8;i++) m = fmaxf(m, v[i]);
  #pragma unroll
  for (int o=16;o;o>>=1) m = fmaxf(m, __shfl_xor_sync(0xffffffffu, m, o));

  __shared__ float red[8];
  __shared__ float bmax, bsum;
  if ((t&31)==0) red[t>>5] = m;
  __syncthreads();
  if (t==0){
    float mm = red[0];
    #pragma unroll
    for (int i=1;i<8;i++) mm = fmaxf(mm, red[i]);
    bmax = mm;
  }
  __syncthreads();
  m = bmax;

  float s = 0.f;
  #pragma unroll
  for (int i=0;i<8;i++){ v[i] = __expf(v[i]-m); s += v[i]; }
  #pragma unroll
  for (int o=16;o;o>>=1) s += __shfl_xor_sync(0xffffffffu, s, o);
  if ((t&31)==0) red[t>>5] = s;
  __syncthreads();
  if (t==0){
    float ss = 0.f;
    #pragma unroll
    for (int i=0;i<8;i++) ss += red[i];
    bsum = ss;
  }
  __syncthreads();
  float inv = 1.f / bsum;

  // write tf32-rounded probs (valid f32 bit patterns) for the PV GEMM
  *(float4*)(S + t*8)     = make_float4(round_tf32(v[0]*inv), round_tf32(v[1]*inv),
                                        round_tf32(v[2]*inv), round_tf32(v[3]*inv));
  *(float4*)(S + t*8 + 4) = make_float4(round_tf32(v[4]*inv), round_tf32(v[5]*inv),
                                        round_tf32(v[6]*inv), round_tf32(v[7]*inv));
}

__global__ __launch_bounds__(NTHR, 2) void pv_kernel(float* __restrict__ out)
{
  extern __shared__ char smem[];
  const int b = blockIdx.z;
  const int m0 = blockIdx.y*BM, n0 = blockIdx.x*BN;
  const float* A = g_s + (size_t)b*SEQ*SEQ + (size_t)m0*SEQ;
  const float* B = g_v + (size_t)b*SEQ*VD + n0;
  float* O       = out + (size_t)b*SEQ*VD;

  float acc[4][4][4];
  #pragma unroll
  for (int i=0;i<4;i++)
    #pragma unroll
    for (int j=0;j<4;j++)
      #pragma unroll
      for (int l=0;l<4;l++) acc[i][j][l]=0.f;

  gemm_cp_core<false>(A, SEQ, B, VD, SEQ/BK, smem, acc);

  const int lane = threadIdx.x & 31, warp = threadIdx.x >> 5;
  const int rowB = m0 + (warp&1)*64 + (lane>>2);
  const int colB = n0 + (warp>>1)*32 + (lane&3)*2;
  #pragma unroll
  for (int mi=0; mi<4; mi++){
    #pragma unroll
    for (int ni=0; ni<4; ni++){
      int c0 = colB + ni*8;
      #pragma unroll
      for (int h=0; h<2; h++){
        int r = rowB + mi*16 + h*8;
        O[(size_t)r*VD + c0]   = acc[mi][ni][h*2+0];
        O[(size_t)r*VD + c0+1] = acc[mi][ni][h*2+1];
      }
    }
  }
}

// ------------------------- launch -------------------------

extern "C" void kernel_launch(void* const* d_in, const int* in_sizes, int n_in,
                              void* d_out, int out_size)
{
  (void)in_sizes; (void)n_in; (void)out_size;
  const float* x  = (const float*)d_in[0];
  const float* Wq = (const float*)d_in[1];
  const float* bq = (const float*)d_in[2];
  const float* Wk = (const float*)d_in[3];
  const float* bk = (const float*)d_in[4];
  const float* Wv = (const float*)d_in[5];
  const float* bv = (const float*)d_in[6];
  float* out = (float*)d_out;

  const int QK_SMEM = STAGES*(A_BYTES + BK_BYTES);   // 81920
  const int PV_SMEM = STAGES*(A_BYTES + BN_BYTES);   // 75776
  static bool attr_done = false;
  if (!attr_done){
    cudaFuncSetAttribute(qk_kernel, cudaFuncAttributeMaxDynamicSharedMemorySize, QK_SMEM);
    cudaFuncSetAttribute(pv_kernel, cudaFuncAttributeMaxDynamicSharedMemorySize, PV_SMEM);
    attr_done = true;
  }

  dim3 gp(QD/BN, MTOT/BM, 3);        // 4 x 128 x 3
  proj_kernel<<<gp, NTHR>>>(x, Wq, bq, Wk, bk, Wv, bv);

  dim3 gqk(SEQ/BN, SEQ/BM, BATCH);   // 16 x 16 x 8
  qk_kernel<<<gqk, NTHR, QK_SMEM>>>();

  softmax_kernel<<<MTOT, 256>>>();   // 16384 rows

  dim3 gpv(VD/BN, SEQ/BM, BATCH);    // 4 x 16 x 8
  pv_kernel<<<gpv, NTHR, PV_SMEM>>>(out);
}